// round 2
// baseline (speedup 1.0000x reference)
#include <cuda_runtime.h>
#include <cuda_bf16.h>
#include <math.h>

#define N_NODES 25000
#define N_EDGES 400000
#define D_NODE 512
#define D_EDGE 512
#define D_IN   1024
#define D_HID  512
#define D_OUT  512
#define LN_EPS 1e-5f

// ---------------- scratch (device globals; no cudaMalloc allowed) ----------
__device__ int   g_count[N_NODES];
__device__ int   g_off[N_NODES + 1];
__device__ int   g_cursor[N_NODES];
__device__ int   g_csr[N_EDGES];
__device__ float g_cat[(size_t)N_NODES * D_IN];   // [agg | nfeat]
__device__ float g_h[(size_t)N_NODES * D_HID];    // silu(cat@w1+b1)
__device__ float g_y[(size_t)N_NODES * D_OUT];    // h@w2+b2 (pre-LN)

// ---------------- CSR build ------------------------------------------------
__global__ void zero_count_kernel() {
    int i = blockIdx.x * blockDim.x + threadIdx.x;
    if (i < N_NODES) g_count[i] = 0;
}

__global__ void hist_kernel(const int* __restrict__ dst_idx) {
    int e = blockIdx.x * blockDim.x + threadIdx.x;
    if (e < N_EDGES) atomicAdd(&g_count[dst_idx[e]], 1);
}

// single-block exclusive scan of g_count -> g_off (and g_cursor copy)
__global__ void scan_kernel() {
    const int CH = 25;  // 1024 * 25 = 25600 >= 25000
    __shared__ int s[1024];
    int t = threadIdx.x;
    int base = t * CH;
    int local[CH];
    int sum = 0;
#pragma unroll
    for (int i = 0; i < CH; i++) {
        int idx = base + i;
        int v = (idx < N_NODES) ? g_count[idx] : 0;
        local[i] = sum;
        sum += v;
    }
    s[t] = sum;
    __syncthreads();
    // Hillis-Steele inclusive scan over 1024 partials
    for (int d = 1; d < 1024; d <<= 1) {
        int v = 0;
        if (t >= d) v = s[t - d];
        __syncthreads();
        if (t >= d) s[t] += v;
        __syncthreads();
    }
    int excl = (t > 0) ? s[t - 1] : 0;
#pragma unroll
    for (int i = 0; i < CH; i++) {
        int idx = base + i;
        if (idx < N_NODES) {
            int o = excl + local[i];
            g_off[idx] = o;
            g_cursor[idx] = o;
        }
    }
    if (t == 1023) g_off[N_NODES] = s[1023];
}

__global__ void fill_kernel(const int* __restrict__ dst_idx) {
    int e = blockIdx.x * blockDim.x + threadIdx.x;
    if (e < N_EDGES) {
        int p = atomicAdd(&g_cursor[dst_idx[e]], 1);
        g_csr[p] = e;
    }
}

// ---------------- aggregate + concat --------------------------------------
// one CTA (128 threads) per node; each thread owns a float4 column slice
__global__ void agg_concat_kernel(const float* __restrict__ efeat,
                                  const float* __restrict__ nfeat) {
    int n = blockIdx.x;
    int c = threadIdx.x * 4;
    float4 acc = make_float4(0.f, 0.f, 0.f, 0.f);
    int s = g_off[n];
    int e = g_off[n + 1];
    for (int i = s; i < e; i++) {
        int ed = g_csr[i];
        const float4 v = *(const float4*)(efeat + (size_t)ed * D_EDGE + c);
        acc.x += v.x; acc.y += v.y; acc.z += v.z; acc.w += v.w;
    }
    *(float4*)(g_cat + (size_t)n * D_IN + c) = acc;
    *(float4*)(g_cat + (size_t)n * D_IN + D_EDGE + c) =
        *(const float4*)(nfeat + (size_t)n * D_NODE + c);
}

// ---------------- efeat passthrough copy -----------------------------------
__global__ void copy_kernel(const float4* __restrict__ src, float4* __restrict__ dst, int n4) {
    int i = blockIdx.x * blockDim.x + threadIdx.x;
    if (i < n4) dst[i] = src[i];
}

// ---------------- fp32 SGEMM (128x128x16, 8x8 microtile) -------------------
template <bool SILU>
__global__ __launch_bounds__(256) void sgemm_kernel(
    const float* __restrict__ A, const float* __restrict__ B,
    const float* __restrict__ bias, float* __restrict__ C,
    int M, int N, int K)
{
    const int BM = 128, BN = 128, BK = 16;
    __shared__ float As[BK][BM];
    __shared__ float Bs[BK][BN];
    int tid = threadIdx.x;          // 0..255
    int tx = tid % 16;              // col micro index
    int ty = tid / 16;              // row micro index
    int rowBase = blockIdx.y * BM;
    int colBase = blockIdx.x * BN;

    float acc[8][8];
#pragma unroll
    for (int i = 0; i < 8; i++)
#pragma unroll
        for (int j = 0; j < 8; j++) acc[i][j] = 0.f;

    for (int k0 = 0; k0 < K; k0 += BK) {
        // A tile: 128 rows x 16 k (store transposed into As[k][row])
#pragma unroll
        for (int l = 0; l < 2; l++) {
            int idx = tid + l * 256;      // 0..511
            int r   = idx >> 2;           // 0..127
            int c4  = (idx & 3) * 4;      // 0,4,8,12
            int gr  = rowBase + r;
            float4 v = make_float4(0.f, 0.f, 0.f, 0.f);
            if (gr < M) v = *(const float4*)(A + (size_t)gr * K + k0 + c4);
            As[c4 + 0][r] = v.x;
            As[c4 + 1][r] = v.y;
            As[c4 + 2][r] = v.z;
            As[c4 + 3][r] = v.w;
        }
        // B tile: 16 k x 128 cols
#pragma unroll
        for (int l = 0; l < 2; l++) {
            int idx = tid + l * 256;
            int r   = idx >> 5;           // 0..15
            int c4  = (idx & 31) * 4;     // 0..124
            float4 v = *(const float4*)(B + (size_t)(k0 + r) * N + colBase + c4);
            *(float4*)&Bs[r][c4] = v;
        }
        __syncthreads();
#pragma unroll
        for (int k = 0; k < BK; k++) {
            float a[8], b[8];
            *(float4*)&a[0] = *(float4*)&As[k][ty * 8];
            *(float4*)&a[4] = *(float4*)&As[k][ty * 8 + 4];
            *(float4*)&b[0] = *(float4*)&Bs[k][tx * 8];
            *(float4*)&b[4] = *(float4*)&Bs[k][tx * 8 + 4];
#pragma unroll
            for (int i = 0; i < 8; i++)
#pragma unroll
                for (int j = 0; j < 8; j++)
                    acc[i][j] = fmaf(a[i], b[j], acc[i][j]);
        }
        __syncthreads();
    }

#pragma unroll
    for (int i = 0; i < 8; i++) {
        int gr = rowBase + ty * 8 + i;
        if (gr >= M) continue;
#pragma unroll
        for (int j = 0; j < 8; j += 4) {
            int gc = colBase + tx * 8 + j;
            float4 v;
            v.x = acc[i][j + 0] + bias[gc + 0];
            v.y = acc[i][j + 1] + bias[gc + 1];
            v.z = acc[i][j + 2] + bias[gc + 2];
            v.w = acc[i][j + 3] + bias[gc + 3];
            if (SILU) {
                v.x = v.x / (1.f + __expf(-v.x));
                v.y = v.y / (1.f + __expf(-v.y));
                v.z = v.z / (1.f + __expf(-v.z));
                v.w = v.w / (1.f + __expf(-v.w));
            }
            *(float4*)(C + (size_t)gr * N + gc) = v;
        }
    }
}

// ---------------- LayerNorm + residual -------------------------------------
__global__ void ln_residual_kernel(const float* __restrict__ nfeat,
                                   const float* __restrict__ gamma,
                                   const float* __restrict__ beta,
                                   float* __restrict__ out) {
    int n = blockIdx.x;
    int c = threadIdx.x * 4;
    const float4 v = *(const float4*)(g_y + (size_t)n * D_OUT + c);

    __shared__ float sm[4];
    __shared__ float sm2[4];
    int lane = threadIdx.x & 31;
    int w = threadIdx.x >> 5;

    float s = v.x + v.y + v.z + v.w;
#pragma unroll
    for (int o = 16; o > 0; o >>= 1) s += __shfl_xor_sync(0xffffffffu, s, o);
    if (lane == 0) sm[w] = s;
    __syncthreads();
    float mu = (sm[0] + sm[1] + sm[2] + sm[3]) * (1.f / 512.f);

    float dx = v.x - mu, dy = v.y - mu, dz = v.z - mu, dw = v.w - mu;
    float sq = dx * dx + dy * dy + dz * dz + dw * dw;
#pragma unroll
    for (int o = 16; o > 0; o >>= 1) sq += __shfl_xor_sync(0xffffffffu, sq, o);
    if (lane == 0) sm2[w] = sq;
    __syncthreads();
    float var = (sm2[0] + sm2[1] + sm2[2] + sm2[3]) * (1.f / 512.f);
    float inv = rsqrtf(var + LN_EPS);

    const float4 g = *(const float4*)(gamma + c);
    const float4 b = *(const float4*)(beta + c);
    const float4 nf = *(const float4*)(nfeat + (size_t)n * D_NODE + c);
    float4 o4;
    o4.x = dx * inv * g.x + b.x + nf.x;
    o4.y = dy * inv * g.y + b.y + nf.y;
    o4.z = dz * inv * g.z + b.z + nf.z;
    o4.w = dw * inv * g.w + b.w + nf.w;
    *(float4*)(out + (size_t)n * D_OUT + c) = o4;
}

// ---------------- launch ----------------------------------------------------
extern "C" void kernel_launch(void* const* d_in, const int* in_sizes, int n_in,
                              void* d_out, int out_size) {
    const float* efeat   = (const float*)d_in[0];
    const float* nfeat   = (const float*)d_in[1];
    const int*   dst_idx = (const int*)  d_in[2];
    const float* w1      = (const float*)d_in[3];
    const float* b1      = (const float*)d_in[4];
    const float* w2      = (const float*)d_in[5];
    const float* b2      = (const float*)d_in[6];
    const float* gamma   = (const float*)d_in[7];
    const float* beta    = (const float*)d_in[8];

    // Resolve true DEVICE addresses of the scratch symbols. Passing the bare
    // symbol name from host code passes the host shadow address, which on
    // GB300 (ATS, pageableMemoryAccess=1) is silently readable/writable from
    // the GPU -> R1's "GEMM reads zeros, writes to host memory" failure.
    float *cat_p = nullptr, *h_p = nullptr, *y_p = nullptr;
    cudaGetSymbolAddress((void**)&cat_p, g_cat);
    cudaGetSymbolAddress((void**)&h_p,   g_h);
    cudaGetSymbolAddress((void**)&y_p,   g_y);

    float* out = (float*)d_out;
    float* out_nodes;
    const long long full = (long long)N_EDGES * D_EDGE + (long long)N_NODES * D_OUT;
    if ((long long)out_size >= full) {
        // passthrough efeat into the first section
        int n4 = (N_EDGES * D_EDGE) / 4;  // 51.2M float4
        copy_kernel<<<(n4 + 255) / 256, 256>>>((const float4*)efeat, (float4*)out, n4);
        out_nodes = out + (size_t)N_EDGES * D_EDGE;
    } else {
        out_nodes = out;  // only node features checked
    }

    // CSR build
    zero_count_kernel<<<(N_NODES + 255) / 256, 256>>>();
    hist_kernel<<<(N_EDGES + 255) / 256, 256>>>(dst_idx);
    scan_kernel<<<1, 1024>>>();
    fill_kernel<<<(N_EDGES + 255) / 256, 256>>>(dst_idx);

    // aggregate + concat
    agg_concat_kernel<<<N_NODES, 128>>>(efeat, nfeat);

    // MLP
    {
        dim3 grid(D_HID / 128, (N_NODES + 127) / 128);
        sgemm_kernel<true><<<grid, 256>>>(cat_p, w1, b1, h_p, N_NODES, D_HID, D_IN);
    }
    {
        dim3 grid(D_OUT / 128, (N_NODES + 127) / 128);
        sgemm_kernel<false><<<grid, 256>>>(h_p, w2, b2, y_p, N_NODES, D_OUT, D_HID);
    }

    // LayerNorm + residual
    ln_residual_kernel<<<N_NODES, 128>>>(nfeat, gamma, beta, out_nodes);
}

// round 4
// speedup vs baseline: 1.8120x; 1.8120x over previous
#include <cuda_runtime.h>
#include <cuda_bf16.h>
#include <math.h>
#include <stdint.h>

#define N_NODES 25000
#define N_EDGES 400000
#define D_NODE 512
#define D_EDGE 512
#define D_IN   1024
#define D_HID  512
#define D_OUT  512
#define LN_EPS 1e-5f

// ---------------- scratch (device globals; no cudaMalloc allowed) ----------
__device__ int   g_count[N_NODES];
__device__ int   g_off[N_NODES + 1];
__device__ int   g_cursor[N_NODES];
__device__ int   g_csr[N_EDGES];
__device__ float g_cat[(size_t)N_NODES * D_IN];   // [agg | nfeat], tf32-rounded
__device__ float g_h[(size_t)N_NODES * D_HID];    // silu(cat@w1+b1), tf32-rounded
__device__ float g_y[(size_t)N_NODES * D_OUT];    // h@w2+b2 (pre-LN)
__device__ float g_w1t[(size_t)D_HID * D_IN];     // w1^T [512,1024], tf32-rounded
__device__ float g_w2t[(size_t)D_OUT * D_HID];    // w2^T [512,512], tf32-rounded

// ---------------- small helpers ---------------------------------------------
__device__ __forceinline__ float rna_tf32(float x) {
    float r;
    asm("cvt.rna.tf32.f32 %0, %1;" : "=f"(r) : "f"(x));
    return r;
}

__device__ __forceinline__ uint32_t smem_u32_of(const void* p) {
    uint32_t a;
    asm("{ .reg .u64 t; cvta.to.shared.u64 t, %1; cvt.u32.u64 %0, t; }"
        : "=r"(a) : "l"(p));
    return a;
}

__device__ __forceinline__ void cp16(uint32_t dst, const void* src) {
    asm volatile("cp.async.cg.shared.global [%0], [%1], 16;" :: "r"(dst), "l"(src));
}

__device__ __forceinline__ void mma_tf32(float* c, const uint32_t* a, const uint32_t* b) {
    asm volatile(
        "mma.sync.aligned.m16n8k8.row.col.f32.tf32.tf32.f32 "
        "{%0,%1,%2,%3}, {%4,%5,%6,%7}, {%8,%9}, {%0,%1,%2,%3};"
        : "+f"(c[0]), "+f"(c[1]), "+f"(c[2]), "+f"(c[3])
        : "r"(a[0]), "r"(a[1]), "r"(a[2]), "r"(a[3]), "r"(b[0]), "r"(b[1]));
}

// ---------------- CSR build ------------------------------------------------
__global__ void zero_count_kernel() {
    int i = blockIdx.x * blockDim.x + threadIdx.x;
    if (i < N_NODES) g_count[i] = 0;
}

__global__ void hist_kernel(const int* __restrict__ dst_idx) {
    int e = blockIdx.x * blockDim.x + threadIdx.x;
    if (e < N_EDGES) atomicAdd(&g_count[dst_idx[e]], 1);
}

__global__ void scan_kernel() {
    const int CH = 25;
    __shared__ int s[1024];
    int t = threadIdx.x;
    int base = t * CH;
    int local[CH];
    int sum = 0;
#pragma unroll
    for (int i = 0; i < CH; i++) {
        int idx = base + i;
        int v = (idx < N_NODES) ? g_count[idx] : 0;
        local[i] = sum;
        sum += v;
    }
    s[t] = sum;
    __syncthreads();
    for (int d = 1; d < 1024; d <<= 1) {
        int v = 0;
        if (t >= d) v = s[t - d];
        __syncthreads();
        if (t >= d) s[t] += v;
        __syncthreads();
    }
    int excl = (t > 0) ? s[t - 1] : 0;
#pragma unroll
    for (int i = 0; i < CH; i++) {
        int idx = base + i;
        if (idx < N_NODES) {
            int o = excl + local[i];
            g_off[idx] = o;
            g_cursor[idx] = o;
        }
    }
    if (t == 1023) g_off[N_NODES] = s[1023];
}

__global__ void fill_kernel(const int* __restrict__ dst_idx) {
    int e = blockIdx.x * blockDim.x + threadIdx.x;
    if (e < N_EDGES) {
        int p = atomicAdd(&g_cursor[dst_idx[e]], 1);
        g_csr[p] = e;
    }
}

// ---------------- aggregate + concat (tf32-rounded output) ------------------
__global__ void agg_concat_kernel(const float* __restrict__ efeat,
                                  const float* __restrict__ nfeat) {
    int n = blockIdx.x;
    int c = threadIdx.x * 4;
    float4 acc = make_float4(0.f, 0.f, 0.f, 0.f);
    int s = g_off[n];
    int e = g_off[n + 1];
    for (int i = s; i < e; i++) {
        int ed = g_csr[i];
        const float4 v = *(const float4*)(efeat + (size_t)ed * D_EDGE + c);
        acc.x += v.x; acc.y += v.y; acc.z += v.z; acc.w += v.w;
    }
    float4 o;
    o.x = rna_tf32(acc.x); o.y = rna_tf32(acc.y);
    o.z = rna_tf32(acc.z); o.w = rna_tf32(acc.w);
    *(float4*)(g_cat + (size_t)n * D_IN + c) = o;
    const float4 nf = *(const float4*)(nfeat + (size_t)n * D_NODE + c);
    float4 o2;
    o2.x = rna_tf32(nf.x); o2.y = rna_tf32(nf.y);
    o2.z = rna_tf32(nf.z); o2.w = rna_tf32(nf.w);
    *(float4*)(g_cat + (size_t)n * D_IN + D_EDGE + c) = o2;
}

// ---------------- weight transpose + tf32 round -----------------------------
__global__ void transpose_round_kernel(const float* __restrict__ src,
                                       float* __restrict__ dst, int K, int N) {
    __shared__ float t[32][33];
    int k0 = blockIdx.x * 32, n0 = blockIdx.y * 32;
    int x = threadIdx.x, y0 = threadIdx.y;  // block (32, 8)
#pragma unroll
    for (int d = 0; d < 4; d++) {
        int k = k0 + y0 + d * 8;
        t[y0 + d * 8][x] = src[(size_t)k * N + n0 + x];
    }
    __syncthreads();
#pragma unroll
    for (int d = 0; d < 4; d++) {
        int n = n0 + y0 + d * 8;
        dst[(size_t)n * K + k0 + x] = rna_tf32(t[x][y0 + d * 8]);
    }
}

// ---------------- efeat passthrough copy -----------------------------------
__global__ void copy_kernel(const float4* __restrict__ src, float4* __restrict__ dst, int n4) {
    int i = blockIdx.x * blockDim.x + threadIdx.x;
    if (i < n4) dst[i] = src[i];
}

// ---------------- tf32 mma.sync GEMM: C[M,N] = A[M,K] @ Bt[N,K]^T -----------
// CTA tile 128x128, BK=32 double-buffered cp.async. 8 warps (2x4), warp tile
// 64x32 = 4x4 m16n8k8 atoms. Smem tiles [row][k] with stride 36 (pad) ->
// conflict-free fragment LDS.
#define GS_STRIDE 36
#define GS_TILE   (128 * GS_STRIDE * 4)       // bytes per (A or B) tile: 18432
#define GS_STAGE  (2 * GS_TILE)               // 36864
#define GS_TOTAL  (2 * GS_STAGE)              // 73728

template <bool SILU>
__global__ void __launch_bounds__(256) mma_gemm_kernel(
    const float* __restrict__ A, const float* __restrict__ Bt,
    const float* __restrict__ bias, float* __restrict__ C,
    int M, int K)
{
    extern __shared__ char smem[];
    float* sf = (float*)smem;
    const uint32_t sb = smem_u32_of(smem);
    const int tid = threadIdx.x;
    const int lane = tid & 31;
    const int wid = tid >> 5;
    const int warpRow = wid >> 2;          // 0..1
    const int warpCol = wid & 3;           // 0..3
    const int rowBase = blockIdx.y * 128;
    const int colBase = blockIdx.x * 128;
    const int NC = K >> 5;

    // loader: A tile rows [rowBase,+128) x k32 ; B tile rows [colBase,+128) x k32
    auto load_chunk = [&](int c, int s) {
        const int kc0 = c << 5;
        const uint32_t stg = (uint32_t)(s * GS_STAGE);
        // 1024 segs of 16B for A, 1024 for B; 256 threads x 4 each
#pragma unroll
        for (int i = 0; i < 4; i++) {
            int idx = tid + (i << 8);          // 0..1023
            int r = idx >> 3, seg = idx & 7;
            int gr = rowBase + r;
            if (gr >= M) gr = M - 1;
            cp16(sb + stg + (uint32_t)(r * (GS_STRIDE * 4) + seg * 16),
                 A + (size_t)gr * K + kc0 + seg * 4);
        }
#pragma unroll
        for (int i = 0; i < 4; i++) {
            int idx = tid + (i << 8);
            int r = idx >> 3, seg = idx & 7;
            cp16(sb + stg + GS_TILE + (uint32_t)(r * (GS_STRIDE * 4) + seg * 16),
                 Bt + (size_t)(colBase + r) * K + kc0 + seg * 4);
        }
        asm volatile("cp.async.commit_group;" ::: "memory");
    };

    float acc[4][4][4];
#pragma unroll
    for (int i = 0; i < 4; i++)
#pragma unroll
        for (int j = 0; j < 4; j++)
#pragma unroll
            for (int r = 0; r < 4; r++) acc[i][j][r] = 0.f;

    load_chunk(0, 0);
    if (NC > 1) load_chunk(1, 1);

    for (int c = 0; c < NC; c++) {
        const int s = c & 1;
        if (c + 1 < NC) asm volatile("cp.async.wait_group 1;" ::: "memory");
        else            asm volatile("cp.async.wait_group 0;" ::: "memory");
        __syncthreads();

        const float* As = sf + s * (GS_STAGE / 4);
        const float* Bs = As + (GS_TILE / 4);

#pragma unroll
        for (int ks = 0; ks < 4; ks++) {
            const int kc = (ks << 3) + (lane & 3);
            uint32_t af[4][4], bf[4][2];
#pragma unroll
            for (int t = 0; t < 4; t++) {
                int r0 = warpRow * 64 + t * 16 + (lane >> 2);
                af[t][0] = __float_as_uint(As[r0 * GS_STRIDE + kc]);
                af[t][1] = __float_as_uint(As[(r0 + 8) * GS_STRIDE + kc]);
                af[t][2] = __float_as_uint(As[r0 * GS_STRIDE + kc + 4]);
                af[t][3] = __float_as_uint(As[(r0 + 8) * GS_STRIDE + kc + 4]);
            }
#pragma unroll
            for (int t = 0; t < 4; t++) {
                int n0 = warpCol * 32 + t * 8 + (lane >> 2);
                bf[t][0] = __float_as_uint(Bs[n0 * GS_STRIDE + kc]);
                bf[t][1] = __float_as_uint(Bs[n0 * GS_STRIDE + kc + 4]);
            }
#pragma unroll
            for (int mt = 0; mt < 4; mt++)
#pragma unroll
                for (int nt = 0; nt < 4; nt++)
                    mma_tf32(acc[mt][nt], af[mt], bf[nt]);
        }
        __syncthreads();
        if (c + 2 < NC) load_chunk(c + 2, s);
    }

    // epilogue: bias (+ optional silu + tf32 round), write C[M,512]
#pragma unroll
    for (int mt = 0; mt < 4; mt++) {
        int r0 = rowBase + warpRow * 64 + mt * 16 + (lane >> 2);
#pragma unroll
        for (int nt = 0; nt < 4; nt++) {
            int gc = colBase + warpCol * 32 + nt * 8 + ((lane & 3) << 1);
            float bx = bias[gc], by = bias[gc + 1];
#pragma unroll
            for (int h = 0; h < 2; h++) {
                int gr = r0 + h * 8;
                if (gr >= M) continue;
                float vx = acc[mt][nt][h * 2 + 0] + bx;
                float vy = acc[mt][nt][h * 2 + 1] + by;
                if (SILU) {
                    vx = rna_tf32(vx / (1.f + __expf(-vx)));
                    vy = rna_tf32(vy / (1.f + __expf(-vy)));
                }
                float2 o = make_float2(vx, vy);
                *(float2*)(C + (size_t)gr * 512 + gc) = o;
            }
        }
    }
}

// ---------------- LayerNorm + residual -------------------------------------
__global__ void ln_residual_kernel(const float* __restrict__ nfeat,
                                   const float* __restrict__ gamma,
                                   const float* __restrict__ beta,
                                   float* __restrict__ out) {
    int n = blockIdx.x;
    int c = threadIdx.x * 4;
    const float4 v = *(const float4*)(g_y + (size_t)n * D_OUT + c);

    __shared__ float sm[4];
    __shared__ float sm2[4];
    int lane = threadIdx.x & 31;
    int w = threadIdx.x >> 5;

    float s = v.x + v.y + v.z + v.w;
#pragma unroll
    for (int o = 16; o > 0; o >>= 1) s += __shfl_xor_sync(0xffffffffu, s, o);
    if (lane == 0) sm[w] = s;
    __syncthreads();
    float mu = (sm[0] + sm[1] + sm[2] + sm[3]) * (1.f / 512.f);

    float dx = v.x - mu, dy = v.y - mu, dz = v.z - mu, dw = v.w - mu;
    float sq = dx * dx + dy * dy + dz * dz + dw * dw;
#pragma unroll
    for (int o = 16; o > 0; o >>= 1) sq += __shfl_xor_sync(0xffffffffu, sq, o);
    if (lane == 0) sm2[w] = sq;
    __syncthreads();
    float var = (sm2[0] + sm2[1] + sm2[2] + sm2[3]) * (1.f / 512.f);
    float inv = rsqrtf(var + LN_EPS);

    const float4 g = *(const float4*)(gamma + c);
    const float4 b = *(const float4*)(beta + c);
    const float4 nf = *(const float4*)(nfeat + (size_t)n * D_NODE + c);
    float4 o4;
    o4.x = dx * inv * g.x + b.x + nf.x;
    o4.y = dy * inv * g.y + b.y + nf.y;
    o4.z = dz * inv * g.z + b.z + nf.z;
    o4.w = dw * inv * g.w + b.w + nf.w;
    *(float4*)(out + (size_t)n * D_OUT + c) = o4;
}

// ---------------- launch ----------------------------------------------------
extern "C" void kernel_launch(void* const* d_in, const int* in_sizes, int n_in,
                              void* d_out, int out_size) {
    const float* efeat   = (const float*)d_in[0];
    const float* nfeat   = (const float*)d_in[1];
    const int*   dst_idx = (const int*)  d_in[2];
    const float* w1      = (const float*)d_in[3];
    const float* b1      = (const float*)d_in[4];
    const float* w2      = (const float*)d_in[5];
    const float* b2      = (const float*)d_in[6];
    const float* gamma   = (const float*)d_in[7];
    const float* beta    = (const float*)d_in[8];

    // device addresses of scratch symbols (NOT the host shadow — see R1)
    float *cat_p = nullptr, *h_p = nullptr, *y_p = nullptr, *w1t_p = nullptr, *w2t_p = nullptr;
    cudaGetSymbolAddress((void**)&cat_p, g_cat);
    cudaGetSymbolAddress((void**)&h_p,   g_h);
    cudaGetSymbolAddress((void**)&y_p,   g_y);
    cudaGetSymbolAddress((void**)&w1t_p, g_w1t);
    cudaGetSymbolAddress((void**)&w2t_p, g_w2t);

    cudaFuncSetAttribute(mma_gemm_kernel<true>,  cudaFuncAttributeMaxDynamicSharedMemorySize, GS_TOTAL);
    cudaFuncSetAttribute(mma_gemm_kernel<false>, cudaFuncAttributeMaxDynamicSharedMemorySize, GS_TOTAL);

    float* out = (float*)d_out;
    float* out_nodes;
    const long long full = (long long)N_EDGES * D_EDGE + (long long)N_NODES * D_OUT;
    if ((long long)out_size >= full) {
        int n4 = (N_EDGES * D_EDGE) / 4;
        copy_kernel<<<(n4 + 255) / 256, 256>>>((const float4*)efeat, (float4*)out, n4);
        out_nodes = out + (size_t)N_EDGES * D_EDGE;
    } else {
        out_nodes = out;
    }

    // weight transpose + tf32 round
    {
        dim3 b(32, 8);
        transpose_round_kernel<<<dim3(D_IN / 32, D_HID / 32), b>>>(w1, w1t_p, D_IN, D_HID);
        transpose_round_kernel<<<dim3(D_HID / 32, D_OUT / 32), b>>>(w2, w2t_p, D_HID, D_OUT);
    }

    // CSR build
    zero_count_kernel<<<(N_NODES + 255) / 256, 256>>>();
    hist_kernel<<<(N_EDGES + 255) / 256, 256>>>(dst_idx);
    scan_kernel<<<1, 1024>>>();
    fill_kernel<<<(N_EDGES + 255) / 256, 256>>>(dst_idx);

    // aggregate + concat (tf32-rounded)
    agg_concat_kernel<<<N_NODES, 128>>>(efeat, nfeat);

    // MLP on tf32 mma.sync
    const int gridM = (N_NODES + 127) / 128;  // 196
    {
        dim3 grid(D_HID / 128, gridM);
        mma_gemm_kernel<true><<<grid, 256, GS_TOTAL>>>(cat_p, w1t_p, b1, h_p, N_NODES, D_IN);
    }
    {
        dim3 grid(D_OUT / 128, gridM);
        mma_gemm_kernel<false><<<grid, 256, GS_TOTAL>>>(h_p, w2t_p, b2, y_p, N_NODES, D_HID);
    }

    // LayerNorm + residual
    ln_residual_kernel<<<N_NODES, 128>>>(nfeat, gamma, beta, out_nodes);
}

// round 5
// speedup vs baseline: 2.1811x; 1.2037x over previous
#include <cuda_runtime.h>
#include <cuda_bf16.h>
#include <math.h>
#include <stdint.h>

#define N_NODES 25000
#define N_EDGES 400000
#define D_NODE 512
#define D_EDGE 512
#define D_IN   1024
#define D_HID  512
#define D_OUT  512
#define LN_EPS 1e-5f
#define SCAN_NB 25   // ceil(25000/1024)

// ---------------- scratch (device globals; no cudaMalloc allowed) ----------
__device__ int   g_count[N_NODES];
__device__ int   g_off[N_NODES + 1];
__device__ int   g_cursor[N_NODES];
__device__ int   g_csr[N_EDGES];
__device__ int   g_blocksum[SCAN_NB];
__device__ int   g_blockbase[SCAN_NB];
__device__ float g_cat[(size_t)N_NODES * D_IN];   // [agg | nfeat], tf32-rounded
__device__ float g_h[(size_t)N_NODES * D_HID];    // silu(cat@w1+b1), tf32-rounded
__device__ float g_y[(size_t)N_NODES * D_OUT];    // h@w2+b2 (pre-LN)
__device__ float g_w1t[(size_t)D_HID * D_IN];     // w1^T [512,1024], tf32-rounded
__device__ float g_w2t[(size_t)D_OUT * D_HID];    // w2^T [512,512], tf32-rounded

// ---------------- small helpers ---------------------------------------------
__device__ __forceinline__ float rna_tf32(float x) {
    float r;
    asm("cvt.rna.tf32.f32 %0, %1;" : "=f"(r) : "f"(x));
    return r;
}

__device__ __forceinline__ uint32_t smem_u32_of(const void* p) {
    uint32_t a;
    asm("{ .reg .u64 t; cvta.to.shared.u64 t, %1; cvt.u32.u64 %0, t; }"
        : "=r"(a) : "l"(p));
    return a;
}

__device__ __forceinline__ void cp16(uint32_t dst, const void* src) {
    asm volatile("cp.async.cg.shared.global [%0], [%1], 16;" :: "r"(dst), "l"(src));
}

__device__ __forceinline__ void mma_tf32(float* c, const uint32_t* a, const uint32_t* b) {
    asm volatile(
        "mma.sync.aligned.m16n8k8.row.col.f32.tf32.tf32.f32 "
        "{%0,%1,%2,%3}, {%4,%5,%6,%7}, {%8,%9}, {%0,%1,%2,%3};"
        : "+f"(c[0]), "+f"(c[1]), "+f"(c[2]), "+f"(c[3])
        : "r"(a[0]), "r"(a[1]), "r"(a[2]), "r"(a[3]), "r"(b[0]), "r"(b[1]));
}

// ---------------- CSR build ------------------------------------------------
__global__ void zero_count_kernel() {
    int i = blockIdx.x * blockDim.x + threadIdx.x;
    if (i < N_NODES) g_count[i] = 0;
}

__global__ void hist_kernel(const int* __restrict__ dst_idx) {
    int e = blockIdx.x * blockDim.x + threadIdx.x;
    if (e < N_EDGES) atomicAdd(&g_count[dst_idx[e]], 1);
}

// 3-phase multi-block exclusive scan of g_count -> g_off / g_cursor
__global__ void scan1_kernel() {   // grid SCAN_NB, block 1024
    __shared__ int s[1024];
    int b = blockIdx.x, t = threadIdx.x;
    int idx = b * 1024 + t;
    int v = (idx < N_NODES) ? g_count[idx] : 0;
    s[t] = v;
    __syncthreads();
    for (int d = 1; d < 1024; d <<= 1) {
        int x = 0;
        if (t >= d) x = s[t - d];
        __syncthreads();
        if (t >= d) s[t] += x;
        __syncthreads();
    }
    if (idx < N_NODES) g_off[idx] = s[t] - v;  // exclusive within block
    if (t == 1023) g_blocksum[b] = s[1023];
}

__global__ void scan2_kernel() {   // 1 block, 32 threads
    int t = threadIdx.x;
    int orig = (t < SCAN_NB) ? g_blocksum[t] : 0;
    int v = orig;
#pragma unroll
    for (int d = 1; d < 32; d <<= 1) {
        int x = __shfl_up_sync(0xffffffffu, v, d);
        if (t >= d) v += x;
    }
    if (t < SCAN_NB) g_blockbase[t] = v - orig;   // exclusive
    if (t == SCAN_NB - 1) g_off[N_NODES] = v;     // total
}

__global__ void scan3_kernel() {   // grid SCAN_NB, block 1024
    int b = blockIdx.x, t = threadIdx.x;
    int idx = b * 1024 + t;
    if (idx < N_NODES) {
        int o = g_off[idx] + g_blockbase[b];
        g_off[idx] = o;
        g_cursor[idx] = o;
    }
}

__global__ void fill_kernel(const int* __restrict__ dst_idx) {
    int e = blockIdx.x * blockDim.x + threadIdx.x;
    if (e < N_EDGES) {
        int p = atomicAdd(&g_cursor[dst_idx[e]], 1);
        g_csr[p] = e;
    }
}

// ---------------- aggregate + concat (+ fused efeat passthrough) ------------
// one CTA (128 threads) per node; each thread owns a float4 column slice.
// Every edge row appears exactly once in the CSR, so the passthrough write
// out_e[ed] = efeat[ed] rides the same read -> the standalone copy kernel
// (and its extra 819MB read of efeat) is eliminated.
template <bool PASS>
__global__ void agg_concat_kernel(const float* __restrict__ efeat,
                                  const float* __restrict__ nfeat,
                                  float* __restrict__ out_e) {
    int n = blockIdx.x;
    int c = threadIdx.x * 4;
    float4 acc = make_float4(0.f, 0.f, 0.f, 0.f);
    int s = g_off[n];
    int e = g_off[n + 1];
    int i = s;
    for (; i + 1 < e; i += 2) {
        int ed0 = g_csr[i];
        int ed1 = g_csr[i + 1];
        const float4 v0 = __ldcs((const float4*)(efeat + (size_t)ed0 * D_EDGE + c));
        const float4 v1 = __ldcs((const float4*)(efeat + (size_t)ed1 * D_EDGE + c));
        if (PASS) {
            __stcs((float4*)(out_e + (size_t)ed0 * D_EDGE + c), v0);
            __stcs((float4*)(out_e + (size_t)ed1 * D_EDGE + c), v1);
        }
        acc.x += v0.x; acc.y += v0.y; acc.z += v0.z; acc.w += v0.w;
        acc.x += v1.x; acc.y += v1.y; acc.z += v1.z; acc.w += v1.w;
    }
    if (i < e) {
        int ed = g_csr[i];
        const float4 v = __ldcs((const float4*)(efeat + (size_t)ed * D_EDGE + c));
        if (PASS) __stcs((float4*)(out_e + (size_t)ed * D_EDGE + c), v);
        acc.x += v.x; acc.y += v.y; acc.z += v.z; acc.w += v.w;
    }
    float4 o;
    o.x = rna_tf32(acc.x); o.y = rna_tf32(acc.y);
    o.z = rna_tf32(acc.z); o.w = rna_tf32(acc.w);
    *(float4*)(g_cat + (size_t)n * D_IN + c) = o;
    const float4 nf = *(const float4*)(nfeat + (size_t)n * D_NODE + c);
    float4 o2;
    o2.x = rna_tf32(nf.x); o2.y = rna_tf32(nf.y);
    o2.z = rna_tf32(nf.z); o2.w = rna_tf32(nf.w);
    *(float4*)(g_cat + (size_t)n * D_IN + D_EDGE + c) = o2;
}

// ---------------- weight transpose + tf32 round -----------------------------
__global__ void transpose_round_kernel(const float* __restrict__ src,
                                       float* __restrict__ dst, int K, int N) {
    __shared__ float t[32][33];
    int k0 = blockIdx.x * 32, n0 = blockIdx.y * 32;
    int x = threadIdx.x, y0 = threadIdx.y;  // block (32, 8)
#pragma unroll
    for (int d = 0; d < 4; d++) {
        int k = k0 + y0 + d * 8;
        t[y0 + d * 8][x] = src[(size_t)k * N + n0 + x];
    }
    __syncthreads();
#pragma unroll
    for (int d = 0; d < 4; d++) {
        int n = n0 + y0 + d * 8;
        dst[(size_t)n * K + k0 + x] = rna_tf32(t[x][y0 + d * 8]);
    }
}

// ---------------- tf32 mma.sync GEMM: C[M,N] = A[M,K] @ Bt[N,K]^T -----------
// CTA tile 128x128, BK=32 double-buffered cp.async. 8 warps (2x4), warp tile
// 64x32 = 4x4 m16n8k8 atoms. Smem tiles [row][k] with stride 36 (pad) ->
// conflict-free fragment LDS.
#define GS_STRIDE 36
#define GS_TILE   (128 * GS_STRIDE * 4)       // bytes per (A or B) tile: 18432
#define GS_STAGE  (2 * GS_TILE)               // 36864
#define GS_TOTAL  (2 * GS_STAGE)              // 73728

template <bool SILU>
__global__ void __launch_bounds__(256) mma_gemm_kernel(
    const float* __restrict__ A, const float* __restrict__ Bt,
    const float* __restrict__ bias, float* __restrict__ C,
    int M, int K)
{
    extern __shared__ char smem[];
    float* sf = (float*)smem;
    const uint32_t sb = smem_u32_of(smem);
    const int tid = threadIdx.x;
    const int lane = tid & 31;
    const int wid = tid >> 5;
    const int warpRow = wid >> 2;          // 0..1
    const int warpCol = wid & 3;           // 0..3
    const int rowBase = blockIdx.y * 128;
    const int colBase = blockIdx.x * 128;
    const int NC = K >> 5;

    auto load_chunk = [&](int c, int s) {
        const int kc0 = c << 5;
        const uint32_t stg = (uint32_t)(s * GS_STAGE);
#pragma unroll
        for (int i = 0; i < 4; i++) {
            int idx = tid + (i << 8);          // 0..1023
            int r = idx >> 3, seg = idx & 7;
            int gr = rowBase + r;
            if (gr >= M) gr = M - 1;
            cp16(sb + stg + (uint32_t)(r * (GS_STRIDE * 4) + seg * 16),
                 A + (size_t)gr * K + kc0 + seg * 4);
        }
#pragma unroll
        for (int i = 0; i < 4; i++) {
            int idx = tid + (i << 8);
            int r = idx >> 3, seg = idx & 7;
            cp16(sb + stg + GS_TILE + (uint32_t)(r * (GS_STRIDE * 4) + seg * 16),
                 Bt + (size_t)(colBase + r) * K + kc0 + seg * 4);
        }
        asm volatile("cp.async.commit_group;" ::: "memory");
    };

    float acc[4][4][4];
#pragma unroll
    for (int i = 0; i < 4; i++)
#pragma unroll
        for (int j = 0; j < 4; j++)
#pragma unroll
            for (int r = 0; r < 4; r++) acc[i][j][r] = 0.f;

    load_chunk(0, 0);
    if (NC > 1) load_chunk(1, 1);

    for (int c = 0; c < NC; c++) {
        const int s = c & 1;
        if (c + 1 < NC) asm volatile("cp.async.wait_group 1;" ::: "memory");
        else            asm volatile("cp.async.wait_group 0;" ::: "memory");
        __syncthreads();

        const float* As = sf + s * (GS_STAGE / 4);
        const float* Bs = As + (GS_TILE / 4);

#pragma unroll
        for (int ks = 0; ks < 4; ks++) {
            const int kc = (ks << 3) + (lane & 3);
            uint32_t af[4][4], bf[4][2];
#pragma unroll
            for (int t = 0; t < 4; t++) {
                int r0 = warpRow * 64 + t * 16 + (lane >> 2);
                af[t][0] = __float_as_uint(As[r0 * GS_STRIDE + kc]);
                af[t][1] = __float_as_uint(As[(r0 + 8) * GS_STRIDE + kc]);
                af[t][2] = __float_as_uint(As[r0 * GS_STRIDE + kc + 4]);
                af[t][3] = __float_as_uint(As[(r0 + 8) * GS_STRIDE + kc + 4]);
            }
#pragma unroll
            for (int t = 0; t < 4; t++) {
                int n0 = warpCol * 32 + t * 8 + (lane >> 2);
                bf[t][0] = __float_as_uint(Bs[n0 * GS_STRIDE + kc]);
                bf[t][1] = __float_as_uint(Bs[n0 * GS_STRIDE + kc + 4]);
            }
#pragma unroll
            for (int mt = 0; mt < 4; mt++)
#pragma unroll
                for (int nt = 0; nt < 4; nt++)
                    mma_tf32(acc[mt][nt], af[mt], bf[nt]);
        }
        __syncthreads();
        if (c + 2 < NC) load_chunk(c + 2, s);
    }

    // epilogue: bias (+ optional silu + tf32 round), write C[M,512]
#pragma unroll
    for (int mt = 0; mt < 4; mt++) {
        int r0 = rowBase + warpRow * 64 + mt * 16 + (lane >> 2);
#pragma unroll
        for (int nt = 0; nt < 4; nt++) {
            int gc = colBase + warpCol * 32 + nt * 8 + ((lane & 3) << 1);
            float bx = bias[gc], by = bias[gc + 1];
#pragma unroll
            for (int h = 0; h < 2; h++) {
                int gr = r0 + h * 8;
                if (gr >= M) continue;
                float vx = acc[mt][nt][h * 2 + 0] + bx;
                float vy = acc[mt][nt][h * 2 + 1] + by;
                if (SILU) {
                    vx = rna_tf32(vx / (1.f + __expf(-vx)));
                    vy = rna_tf32(vy / (1.f + __expf(-vy)));
                }
                float2 o = make_float2(vx, vy);
                *(float2*)(C + (size_t)gr * 512 + gc) = o;
            }
        }
    }
}

// ---------------- LayerNorm + residual -------------------------------------
__global__ void ln_residual_kernel(const float* __restrict__ nfeat,
                                   const float* __restrict__ gamma,
                                   const float* __restrict__ beta,
                                   float* __restrict__ out) {
    int n = blockIdx.x;
    int c = threadIdx.x * 4;
    const float4 v = *(const float4*)(g_y + (size_t)n * D_OUT + c);

    __shared__ float sm[4];
    __shared__ float sm2[4];
    int lane = threadIdx.x & 31;
    int w = threadIdx.x >> 5;

    float s = v.x + v.y + v.z + v.w;
#pragma unroll
    for (int o = 16; o > 0; o >>= 1) s += __shfl_xor_sync(0xffffffffu, s, o);
    if (lane == 0) sm[w] = s;
    __syncthreads();
    float mu = (sm[0] + sm[1] + sm[2] + sm[3]) * (1.f / 512.f);

    float dx = v.x - mu, dy = v.y - mu, dz = v.z - mu, dw = v.w - mu;
    float sq = dx * dx + dy * dy + dz * dz + dw * dw;
#pragma unroll
    for (int o = 16; o > 0; o >>= 1) sq += __shfl_xor_sync(0xffffffffu, sq, o);
    if (lane == 0) sm2[w] = sq;
    __syncthreads();
    float var = (sm2[0] + sm2[1] + sm2[2] + sm2[3]) * (1.f / 512.f);
    float inv = rsqrtf(var + LN_EPS);

    const float4 g = *(const float4*)(gamma + c);
    const float4 b = *(const float4*)(beta + c);
    const float4 nf = *(const float4*)(nfeat + (size_t)n * D_NODE + c);
    float4 o4;
    o4.x = dx * inv * g.x + b.x + nf.x;
    o4.y = dy * inv * g.y + b.y + nf.y;
    o4.z = dz * inv * g.z + b.z + nf.z;
    o4.w = dw * inv * g.w + b.w + nf.w;
    *(float4*)(out + (size_t)n * D_OUT + c) = o4;
}

// ---------------- launch ----------------------------------------------------
extern "C" void kernel_launch(void* const* d_in, const int* in_sizes, int n_in,
                              void* d_out, int out_size) {
    const float* efeat   = (const float*)d_in[0];
    const float* nfeat   = (const float*)d_in[1];
    const int*   dst_idx = (const int*)  d_in[2];
    const float* w1      = (const float*)d_in[3];
    const float* b1      = (const float*)d_in[4];
    const float* w2      = (const float*)d_in[5];
    const float* b2      = (const float*)d_in[6];
    const float* gamma   = (const float*)d_in[7];
    const float* beta    = (const float*)d_in[8];

    // device addresses of scratch symbols (NOT the host shadow — see R1)
    float *cat_p = nullptr, *h_p = nullptr, *y_p = nullptr, *w1t_p = nullptr, *w2t_p = nullptr;
    cudaGetSymbolAddress((void**)&cat_p, g_cat);
    cudaGetSymbolAddress((void**)&h_p,   g_h);
    cudaGetSymbolAddress((void**)&y_p,   g_y);
    cudaGetSymbolAddress((void**)&w1t_p, g_w1t);
    cudaGetSymbolAddress((void**)&w2t_p, g_w2t);

    cudaFuncSetAttribute(mma_gemm_kernel<true>,  cudaFuncAttributeMaxDynamicSharedMemorySize, GS_TOTAL);
    cudaFuncSetAttribute(mma_gemm_kernel<false>, cudaFuncAttributeMaxDynamicSharedMemorySize, GS_TOTAL);

    float* out = (float*)d_out;
    float* out_nodes;
    const long long full = (long long)N_EDGES * D_EDGE + (long long)N_NODES * D_OUT;
    const bool pass = ((long long)out_size >= full);
    out_nodes = pass ? out + (size_t)N_EDGES * D_EDGE : out;

    // weight transpose + tf32 round
    {
        dim3 b(32, 8);
        transpose_round_kernel<<<dim3(D_IN / 32, D_HID / 32), b>>>(w1, w1t_p, D_IN, D_HID);
        transpose_round_kernel<<<dim3(D_HID / 32, D_OUT / 32), b>>>(w2, w2t_p, D_HID, D_OUT);
    }

    // CSR build
    zero_count_kernel<<<(N_NODES + 255) / 256, 256>>>();
    hist_kernel<<<(N_EDGES + 255) / 256, 256>>>(dst_idx);
    scan1_kernel<<<SCAN_NB, 1024>>>();
    scan2_kernel<<<1, 32>>>();
    scan3_kernel<<<SCAN_NB, 1024>>>();
    fill_kernel<<<(N_EDGES + 255) / 256, 256>>>(dst_idx);

    // aggregate + concat (+ fused efeat passthrough)
    if (pass) agg_concat_kernel<true><<<N_NODES, 128>>>(efeat, nfeat, out);
    else      agg_concat_kernel<false><<<N_NODES, 128>>>(efeat, nfeat, nullptr);

    // MLP on tf32 mma.sync
    const int gridM = (N_NODES + 127) / 128;  // 196
    {
        dim3 grid(D_HID / 128, gridM);
        mma_gemm_kernel<true><<<grid, 256, GS_TOTAL>>>(cat_p, w1t_p, b1, h_p, N_NODES, D_IN);
    }
    {
        dim3 grid(D_OUT / 128, gridM);
        mma_gemm_kernel<false><<<grid, 256, GS_TOTAL>>>(h_p, w2t_p, b2, y_p, N_NODES, D_HID);
    }

    // LayerNorm + residual
    ln_residual_kernel<<<N_NODES, 128>>>(nfeat, gamma, beta, out_nodes);
}

// round 7
// speedup vs baseline: 2.8545x; 1.3088x over previous
#include <cuda_runtime.h>
#include <cuda_fp16.h>
#include <math.h>
#include <stdint.h>

#define N_NODES 25000
#define N_EDGES 400000
#define D_NODE 512
#define D_EDGE 512
#define D_IN   1024
#define D_HID  512
#define D_OUT  512
#define LN_EPS 1e-5f
#define SCAN_NB 25   // ceil(25000/1024)

// ---------------- scratch (device globals; no cudaMalloc allowed) ----------
__device__ int    g_count[N_NODES];
__device__ int    g_off[N_NODES + 1];
__device__ int    g_cursor[N_NODES];
__device__ int    g_csr[N_EDGES];
__device__ int    g_blocksum[SCAN_NB];
__device__ int    g_blockbase[SCAN_NB];
__device__ __half g_cat[(size_t)N_NODES * D_IN];   // [agg | nfeat], fp16
__device__ __half g_h[(size_t)N_NODES * D_HID];    // silu(cat@w1+b1), fp16
__device__ float  g_y[(size_t)N_NODES * D_OUT];    // h@w2+b2 (pre-LN), f32
__device__ __half g_w1t[(size_t)D_HID * D_IN];     // w1^T [512,1024], fp16
__device__ __half g_w2t[(size_t)D_OUT * D_HID];    // w2^T [512,512], fp16

// ---------------- small helpers ---------------------------------------------
__device__ __forceinline__ uint32_t smem_u32_of(const void* p) {
    uint32_t a;
    asm("{ .reg .u64 t; cvta.to.shared.u64 t, %1; cvt.u32.u64 %0, t; }"
        : "=r"(a) : "l"(p));
    return a;
}

__device__ __forceinline__ uint32_t h2_bits(__half2 h) {
    uint32_t u;
    __builtin_memcpy(&u, &h, 4);
    return u;
}

__device__ __forceinline__ void cp16(uint32_t dst, const void* src) {
    asm volatile("cp.async.cg.shared.global [%0], [%1], 16;" :: "r"(dst), "l"(src));
}

__device__ __forceinline__ void mma_fp16(float* c, const uint32_t* a, const uint32_t* b) {
    asm volatile(
        "mma.sync.aligned.m16n8k16.row.col.f32.f16.f16.f32 "
        "{%0,%1,%2,%3}, {%4,%5,%6,%7}, {%8,%9}, {%0,%1,%2,%3};"
        : "+f"(c[0]), "+f"(c[1]), "+f"(c[2]), "+f"(c[3])
        : "r"(a[0]), "r"(a[1]), "r"(a[2]), "r"(a[3]), "r"(b[0]), "r"(b[1]));
}

// ---------------- CSR build ------------------------------------------------
__global__ void zero_count_kernel() {
    int i = blockIdx.x * blockDim.x + threadIdx.x;
    if (i < N_NODES) g_count[i] = 0;
}

__global__ void hist_kernel(const int* __restrict__ dst_idx) {
    int e = blockIdx.x * blockDim.x + threadIdx.x;
    if (e < N_EDGES) atomicAdd(&g_count[dst_idx[e]], 1);
}

// 3-phase multi-block exclusive scan of g_count -> g_off / g_cursor
__global__ void scan1_kernel() {   // grid SCAN_NB, block 1024
    __shared__ int s[1024];
    int b = blockIdx.x, t = threadIdx.x;
    int idx = b * 1024 + t;
    int v = (idx < N_NODES) ? g_count[idx] : 0;
    s[t] = v;
    __syncthreads();
    for (int d = 1; d < 1024; d <<= 1) {
        int x = 0;
        if (t >= d) x = s[t - d];
        __syncthreads();
        if (t >= d) s[t] += x;
        __syncthreads();
    }
    if (idx < N_NODES) g_off[idx] = s[t] - v;  // exclusive within block
    if (t == 1023) g_blocksum[b] = s[1023];
}

__global__ void scan2_kernel() {   // 1 block, 32 threads
    int t = threadIdx.x;
    int orig = (t < SCAN_NB) ? g_blocksum[t] : 0;
    int v = orig;
#pragma unroll
    for (int d = 1; d < 32; d <<= 1) {
        int x = __shfl_up_sync(0xffffffffu, v, d);
        if (t >= d) v += x;
    }
    if (t < SCAN_NB) g_blockbase[t] = v - orig;   // exclusive
    if (t == SCAN_NB - 1) g_off[N_NODES] = v;     // total
}

__global__ void scan3_kernel() {   // grid SCAN_NB, block 1024
    int b = blockIdx.x, t = threadIdx.x;
    int idx = b * 1024 + t;
    if (idx < N_NODES) {
        int o = g_off[idx] + g_blockbase[b];
        g_off[idx] = o;
        g_cursor[idx] = o;
    }
}

__global__ void fill_kernel(const int* __restrict__ dst_idx) {
    int e = blockIdx.x * blockDim.x + threadIdx.x;
    if (e < N_EDGES) {
        int p = atomicAdd(&g_cursor[dst_idx[e]], 1);
        g_csr[p] = e;
    }
}

// ---------------- aggregate + concat (+ fused efeat passthrough) ------------
// one CTA (128 threads) per node; each thread owns a 4-col slice.
// Passthrough write out_e[ed] = efeat[ed] rides the gather read (each edge row
// appears exactly once in the CSR). Output g_cat is fp16.
template <bool PASS>
__global__ void agg_concat_kernel(const float* __restrict__ efeat,
                                  const float* __restrict__ nfeat,
                                  float* __restrict__ out_e) {
    int n = blockIdx.x;
    int c = threadIdx.x * 4;
    float4 acc = make_float4(0.f, 0.f, 0.f, 0.f);
    int s = g_off[n];
    int e = g_off[n + 1];
    int i = s;
    for (; i + 1 < e; i += 2) {
        int ed0 = g_csr[i];
        int ed1 = g_csr[i + 1];
        const float4 v0 = __ldcs((const float4*)(efeat + (size_t)ed0 * D_EDGE + c));
        const float4 v1 = __ldcs((const float4*)(efeat + (size_t)ed1 * D_EDGE + c));
        if (PASS) {
            __stcs((float4*)(out_e + (size_t)ed0 * D_EDGE + c), v0);
            __stcs((float4*)(out_e + (size_t)ed1 * D_EDGE + c), v1);
        }
        acc.x += v0.x; acc.y += v0.y; acc.z += v0.z; acc.w += v0.w;
        acc.x += v1.x; acc.y += v1.y; acc.z += v1.z; acc.w += v1.w;
    }
    if (i < e) {
        int ed = g_csr[i];
        const float4 v = __ldcs((const float4*)(efeat + (size_t)ed * D_EDGE + c));
        if (PASS) __stcs((float4*)(out_e + (size_t)ed * D_EDGE + c), v);
        acc.x += v.x; acc.y += v.y; acc.z += v.z; acc.w += v.w;
    }
    __half2 h0 = __floats2half2_rn(acc.x, acc.y);
    __half2 h1 = __floats2half2_rn(acc.z, acc.w);
    *(uint2*)(g_cat + (size_t)n * D_IN + c) = make_uint2(h2_bits(h0), h2_bits(h1));
    const float4 nf = *(const float4*)(nfeat + (size_t)n * D_NODE + c);
    __half2 h2 = __floats2half2_rn(nf.x, nf.y);
    __half2 h3 = __floats2half2_rn(nf.z, nf.w);
    *(uint2*)(g_cat + (size_t)n * D_IN + D_EDGE + c) = make_uint2(h2_bits(h2), h2_bits(h3));
}

// ---------------- weight transpose + fp16 convert ---------------------------
__global__ void transpose_half_kernel(const float* __restrict__ src,
                                      __half* __restrict__ dst, int K, int N) {
    __shared__ float t[32][33];
    int k0 = blockIdx.x * 32, n0 = blockIdx.y * 32;
    int x = threadIdx.x, y0 = threadIdx.y;  // block (32, 8)
#pragma unroll
    for (int d = 0; d < 4; d++) {
        int k = k0 + y0 + d * 8;
        t[y0 + d * 8][x] = src[(size_t)k * N + n0 + x];
    }
    __syncthreads();
#pragma unroll
    for (int d = 0; d < 4; d++) {
        int n = n0 + y0 + d * 8;
        dst[(size_t)n * K + k0 + x] = __float2half_rn(t[x][y0 + d * 8]);
    }
}

// ---------------- fp16 mma.sync GEMM: C[M,N] = A[M,K] @ Bt[N,K]^T -----------
// CTA tile 128x128, BK=32 double-buffered cp.async. 8 warps (2x4), warp tile
// 64x32 = 4x4 m16n8k16 atoms x 2 k-steps. Smem tiles [row][k] halves with
// stride 40 (80B, 16B-aligned) -> conflict-free fragment LDS.
#define HS_STRIDE 40                          // halves per row
#define HS_TILE   (128 * HS_STRIDE * 2)       // bytes per tile: 10240
#define HS_STAGE  (2 * HS_TILE)               // 20480
#define HS_TOTAL  (2 * HS_STAGE)              // 40960

// OUT_HALF: write C as fp16 (with silu); else f32 (bias only)
template <bool SILU, bool OUT_HALF>
__global__ void __launch_bounds__(256) mma_gemm_kernel(
    const __half* __restrict__ A, const __half* __restrict__ Bt,
    const float* __restrict__ bias, void* __restrict__ Cv,
    int M, int K)
{
    extern __shared__ char smem[];
    const __half* sh = (const __half*)smem;
    const uint32_t sb = smem_u32_of(smem);
    const int tid = threadIdx.x;
    const int lane = tid & 31;
    const int wid = tid >> 5;
    const int warpRow = wid >> 2;          // 0..1
    const int warpCol = wid & 3;           // 0..3
    const int rowBase = blockIdx.y * 128;
    const int colBase = blockIdx.x * 128;
    const int NC = K >> 5;

    // loader: tile rows x 32 halves (64B = 4 x 16B segs); 512 segs per tile
    auto load_chunk = [&](int c, int s) {
        const int kc0 = c << 5;
        const uint32_t stg = (uint32_t)(s * HS_STAGE);
#pragma unroll
        for (int i = 0; i < 2; i++) {
            int idx = tid + (i << 8);          // 0..511
            int r = idx >> 2, seg = idx & 3;
            int gr = rowBase + r;
            if (gr >= M) gr = M - 1;
            cp16(sb + stg + (uint32_t)(r * (HS_STRIDE * 2) + seg * 16),
                 A + (size_t)gr * K + kc0 + seg * 8);
        }
#pragma unroll
        for (int i = 0; i < 2; i++) {
            int idx = tid + (i << 8);
            int r = idx >> 2, seg = idx & 3;
            cp16(sb + stg + HS_TILE + (uint32_t)(r * (HS_STRIDE * 2) + seg * 16),
                 Bt + (size_t)(colBase + r) * K + kc0 + seg * 8);
        }
        asm volatile("cp.async.commit_group;" ::: "memory");
    };

    float acc[4][4][4];
#pragma unroll
    for (int i = 0; i < 4; i++)
#pragma unroll
        for (int j = 0; j < 4; j++)
#pragma unroll
            for (int r = 0; r < 4; r++) acc[i][j][r] = 0.f;

    load_chunk(0, 0);
    if (NC > 1) load_chunk(1, 1);

    for (int c = 0; c < NC; c++) {
        const int s = c & 1;
        if (c + 1 < NC) asm volatile("cp.async.wait_group 1;" ::: "memory");
        else            asm volatile("cp.async.wait_group 0;" ::: "memory");
        __syncthreads();

        const __half* As = sh + s * (HS_STAGE / 2);
        const __half* Bs = As + (HS_TILE / 2);

#pragma unroll
        for (int ks = 0; ks < 2; ks++) {
            const int kc = (ks << 4) + ((lane & 3) << 1);   // k offset of fragment pair
            uint32_t af[4][4], bf[4][2];
#pragma unroll
            for (int t = 0; t < 4; t++) {
                int r0 = warpRow * 64 + t * 16 + (lane >> 2);
                af[t][0] = *(const uint32_t*)(As + r0 * HS_STRIDE + kc);
                af[t][1] = *(const uint32_t*)(As + (r0 + 8) * HS_STRIDE + kc);
                af[t][2] = *(const uint32_t*)(As + r0 * HS_STRIDE + kc + 8);
                af[t][3] = *(const uint32_t*)(As + (r0 + 8) * HS_STRIDE + kc + 8);
            }
#pragma unroll
            for (int t = 0; t < 4; t++) {
                int n0 = warpCol * 32 + t * 8 + (lane >> 2);
                bf[t][0] = *(const uint32_t*)(Bs + n0 * HS_STRIDE + kc);
                bf[t][1] = *(const uint32_t*)(Bs + n0 * HS_STRIDE + kc + 8);
            }
#pragma unroll
            for (int mt = 0; mt < 4; mt++)
#pragma unroll
                for (int nt = 0; nt < 4; nt++)
                    mma_fp16(acc[mt][nt], af[mt], bf[nt]);
        }
        __syncthreads();
        if (c + 2 < NC) load_chunk(c + 2, s);
    }

    // epilogue
#pragma unroll
    for (int mt = 0; mt < 4; mt++) {
        int r0 = rowBase + warpRow * 64 + mt * 16 + (lane >> 2);
#pragma unroll
        for (int nt = 0; nt < 4; nt++) {
            int gc = colBase + warpCol * 32 + nt * 8 + ((lane & 3) << 1);
            float bx = bias[gc], by = bias[gc + 1];
#pragma unroll
            for (int h = 0; h < 2; h++) {
                int gr = r0 + h * 8;
                if (gr >= M) continue;
                float vx = acc[mt][nt][h * 2 + 0] + bx;
                float vy = acc[mt][nt][h * 2 + 1] + by;
                if (SILU) {
                    vx = vx / (1.f + __expf(-vx));
                    vy = vy / (1.f + __expf(-vy));
                }
                if (OUT_HALF) {
                    __half2 hv = __floats2half2_rn(vx, vy);
                    *(uint32_t*)((__half*)Cv + (size_t)gr * 512 + gc) = h2_bits(hv);
                } else {
                    *(float2*)((float*)Cv + (size_t)gr * 512 + gc) = make_float2(vx, vy);
                }
            }
        }
    }
}

// ---------------- LayerNorm + residual -------------------------------------
__global__ void ln_residual_kernel(const float* __restrict__ nfeat,
                                   const float* __restrict__ gamma,
                                   const float* __restrict__ beta,
                                   float* __restrict__ out) {
    int n = blockIdx.x;
    int c = threadIdx.x * 4;
    const float4 v = *(const float4*)(g_y + (size_t)n * D_OUT + c);

    __shared__ float sm[4];
    __shared__ float sm2[4];
    int lane = threadIdx.x & 31;
    int w = threadIdx.x >> 5;

    float s = v.x + v.y + v.z + v.w;
#pragma unroll
    for (int o = 16; o > 0; o >>= 1) s += __shfl_xor_sync(0xffffffffu, s, o);
    if (lane == 0) sm[w] = s;
    __syncthreads();
    float mu = (sm[0] + sm[1] + sm[2] + sm[3]) * (1.f / 512.f);

    float dx = v.x - mu, dy = v.y - mu, dz = v.z - mu, dw = v.w - mu;
    float sq = dx * dx + dy * dy + dz * dz + dw * dw;
#pragma unroll
    for (int o = 16; o > 0; o >>= 1) sq += __shfl_xor_sync(0xffffffffu, sq, o);
    if (lane == 0) sm2[w] = sq;
    __syncthreads();
    float var = (sm2[0] + sm2[1] + sm2[2] + sm2[3]) * (1.f / 512.f);
    float inv = rsqrtf(var + LN_EPS);

    const float4 g = *(const float4*)(gamma + c);
    const float4 b = *(const float4*)(beta + c);
    const float4 nf = *(const float4*)(nfeat + (size_t)n * D_NODE + c);
    float4 o4;
    o4.x = dx * inv * g.x + b.x + nf.x;
    o4.y = dy * inv * g.y + b.y + nf.y;
    o4.z = dz * inv * g.z + b.z + nf.z;
    o4.w = dw * inv * g.w + b.w + nf.w;
    *(float4*)(out + (size_t)n * D_OUT + c) = o4;
}

// ---------------- launch ----------------------------------------------------
extern "C" void kernel_launch(void* const* d_in, const int* in_sizes, int n_in,
                              void* d_out, int out_size) {
    const float* efeat   = (const float*)d_in[0];
    const float* nfeat   = (const float*)d_in[1];
    const int*   dst_idx = (const int*)  d_in[2];
    const float* w1      = (const float*)d_in[3];
    const float* b1      = (const float*)d_in[4];
    const float* w2      = (const float*)d_in[5];
    const float* b2      = (const float*)d_in[6];
    const float* gamma   = (const float*)d_in[7];
    const float* beta    = (const float*)d_in[8];

    // device addresses of scratch symbols (NOT the host shadow — see R1)
    __half *cat_p = nullptr, *h_p = nullptr, *w1t_p = nullptr, *w2t_p = nullptr;
    float  *y_p = nullptr;
    cudaGetSymbolAddress((void**)&cat_p, g_cat);
    cudaGetSymbolAddress((void**)&h_p,   g_h);
    cudaGetSymbolAddress((void**)&y_p,   g_y);
    cudaGetSymbolAddress((void**)&w1t_p, g_w1t);
    cudaGetSymbolAddress((void**)&w2t_p, g_w2t);

    cudaFuncSetAttribute((const void*)mma_gemm_kernel<true, true>,
                         cudaFuncAttributeMaxDynamicSharedMemorySize, HS_TOTAL);
    cudaFuncSetAttribute((const void*)mma_gemm_kernel<false, false>,
                         cudaFuncAttributeMaxDynamicSharedMemorySize, HS_TOTAL);

    float* out = (float*)d_out;
    float* out_nodes;
    const long long full = (long long)N_EDGES * D_EDGE + (long long)N_NODES * D_OUT;
    const bool pass = ((long long)out_size >= full);
    out_nodes = pass ? out + (size_t)N_EDGES * D_EDGE : out;

    // weight transpose + fp16 convert
    {
        dim3 b(32, 8);
        transpose_half_kernel<<<dim3(D_IN / 32, D_HID / 32), b>>>(w1, w1t_p, D_IN, D_HID);
        transpose_half_kernel<<<dim3(D_HID / 32, D_OUT / 32), b>>>(w2, w2t_p, D_HID, D_OUT);
    }

    // CSR build
    zero_count_kernel<<<(N_NODES + 255) / 256, 256>>>();
    hist_kernel<<<(N_EDGES + 255) / 256, 256>>>(dst_idx);
    scan1_kernel<<<SCAN_NB, 1024>>>();
    scan2_kernel<<<1, 32>>>();
    scan3_kernel<<<SCAN_NB, 1024>>>();
    fill_kernel<<<(N_EDGES + 255) / 256, 256>>>(dst_idx);

    // aggregate + concat (+ fused efeat passthrough)
    if (pass) agg_concat_kernel<true><<<N_NODES, 128>>>(efeat, nfeat, out);
    else      agg_concat_kernel<false><<<N_NODES, 128>>>(efeat, nfeat, nullptr);

    // MLP on fp16 mma.sync (f32 accumulate)
    const int gridM = (N_NODES + 127) / 128;  // 196
    {
        dim3 grid(D_HID / 128, gridM);
        mma_gemm_kernel<true, true><<<grid, 256, HS_TOTAL>>>(cat_p, w1t_p, b1, h_p, N_NODES, D_IN);
    }
    {
        dim3 grid(D_OUT / 128, gridM);
        mma_gemm_kernel<false, false><<<grid, 256, HS_TOTAL>>>(h_p, w2t_p, b2, y_p, N_NODES, D_HID);
    }

    // LayerNorm + residual
    ln_residual_kernel<<<N_NODES, 128>>>(nfeat, gamma, beta, out_nodes);
}